// round 2
// baseline (speedup 1.0000x reference)
#include <cuda_runtime.h>
#include <math.h>
#include <stdint.h>

// Problem constants
#define BSZ   4
#define NQ    2048
#define MK    2048
#define DIMX  1024
#define CTXD  1024
#define HEADS 8
#define DHEAD 64
#define INNER 512   // HEADS * DHEAD

// Scratch (allocation-free rule: __device__ globals)
__device__ float g_Q[(size_t)BSZ * NQ * INNER];
__device__ float g_K[(size_t)BSZ * MK * INNER];
__device__ float g_V[(size_t)BSZ * MK * INNER];
__device__ float g_O[(size_t)BSZ * NQ * INNER];

// ----------------------------------------------------------------------------
// SGEMM: C[M,N] = A[M,K] @ W[K,N] (+ bias[n] optional)
// BM=128, BN=64, BK=16, 256 threads, each thread 8x4.
// Assumes M%128==0, N%64==0, K%16==0 (true for all our shapes).
// ----------------------------------------------------------------------------
__global__ __launch_bounds__(256)
void sgemm_kernel(const float* __restrict__ A, const float* __restrict__ W,
                  float* __restrict__ C, const float* __restrict__ bias,
                  int M, int N, int K)
{
    __shared__ float Ast[16][128];   // A transposed: [kk][m]
    __shared__ float Bs[16][64];

    const int tid = threadIdx.x;
    const int tx = tid & 15;         // 0..15 -> n
    const int ty = tid >> 4;         // 0..15 -> m
    const int m0 = blockIdx.y * 128;
    const int n0 = blockIdx.x * 64;

    // A-load mapping: thread t loads row m0 + t/2, k-cols (t%2)*8 .. +7 (2 float4)
    const int lm = tid >> 1;
    const int lk = (tid & 1) * 8;
    // B-load mapping: thread t loads row t/16, cols (t%16)*4 (1 float4)
    const int bkr = tid >> 4;
    const int bn  = (tid & 15) * 4;

    float acc[8][4];
    #pragma unroll
    for (int i = 0; i < 8; i++)
        #pragma unroll
        for (int j = 0; j < 4; j++) acc[i][j] = 0.f;

    for (int k0 = 0; k0 < K; k0 += 16) {
        const float4* ap = (const float4*)(A + (size_t)(m0 + lm) * K + k0 + lk);
        float4 a0 = ap[0];
        float4 a1 = ap[1];
        Ast[lk + 0][lm] = a0.x; Ast[lk + 1][lm] = a0.y;
        Ast[lk + 2][lm] = a0.z; Ast[lk + 3][lm] = a0.w;
        Ast[lk + 4][lm] = a1.x; Ast[lk + 5][lm] = a1.y;
        Ast[lk + 6][lm] = a1.z; Ast[lk + 7][lm] = a1.w;

        float4 b4 = *(const float4*)(W + (size_t)(k0 + bkr) * N + n0 + bn);
        *(float4*)&Bs[bkr][bn] = b4;
        __syncthreads();

        #pragma unroll
        for (int kk = 0; kk < 16; kk++) {
            float a[8], b[4];
            #pragma unroll
            for (int i = 0; i < 8; i++) a[i] = Ast[kk][ty * 8 + i];
            #pragma unroll
            for (int j = 0; j < 4; j++) b[j] = Bs[kk][tx * 4 + j];
            #pragma unroll
            for (int i = 0; i < 8; i++)
                #pragma unroll
                for (int j = 0; j < 4; j++) acc[i][j] = fmaf(a[i], b[j], acc[i][j]);
        }
        __syncthreads();
    }

    #pragma unroll
    for (int i = 0; i < 8; i++) {
        const int m = m0 + ty * 8 + i;
        const int n = n0 + tx * 4;
        float4 v = make_float4(acc[i][0], acc[i][1], acc[i][2], acc[i][3]);
        if (bias) {
            v.x += bias[n + 0]; v.y += bias[n + 1];
            v.z += bias[n + 2]; v.w += bias[n + 3];
        }
        *(float4*)(C + (size_t)m * N + n) = v;
    }
}

// ----------------------------------------------------------------------------
// Flash attention: per (b,h) head, 64-query tile per CTA, online softmax.
// Q/K/V layouts: [B, seq, HEADS*DHEAD] row-major (projection output).
// O same layout. 256 threads (16x16), each thread owns 4 query rows x 4 cols.
// Mask is read as int32 (harness promotes bool; !=0 test is also correct if
// it were float32, since 0x3F800000 != 0).
// Dynamic smem: Qs[64][65], KVs[64][65], Ps[64][65], msk[64]
// ----------------------------------------------------------------------------
#define FLASH_SMEM_FLOATS (3 * 64 * 65 + 64)

__global__ __launch_bounds__(256)
void flash_kernel(const float* __restrict__ Q, const float* __restrict__ K,
                  const float* __restrict__ V, const int* __restrict__ mask,
                  float* __restrict__ O)
{
    extern __shared__ float smem[];
    float (*Qs)[65]  = (float (*)[65])smem;
    float (*KVs)[65] = (float (*)[65])(smem + 64 * 65);
    float (*Ps)[65]  = (float (*)[65])(smem + 2 * 64 * 65);
    float* msk = smem + 3 * 64 * 65;

    const int bh = blockIdx.y;
    const int b = bh / HEADS, h = bh % HEADS;
    const int q0 = blockIdx.x * 64;

    const int tid = threadIdx.x;
    const int tx = tid & 15;     // key/dim column group
    const int ty = tid >> 4;     // query row group

    const float* Qbase = Q + (size_t)b * NQ * INNER + (size_t)h * DHEAD;
    const float* Kbase = K + (size_t)b * MK * INNER + (size_t)h * DHEAD;
    const float* Vbase = V + (size_t)b * MK * INNER + (size_t)h * DHEAD;
    const int* mb = mask + (size_t)b * MK;

    // Load Q tile [64 q][64 d]
    for (int t = tid; t < 64 * 64; t += 256) {
        int r = t >> 6, c = t & 63;
        Qs[r][c] = Qbase[(size_t)(q0 + r) * INNER + c];
    }

    float m_i[4], l_i[4], acc[4][4];
    #pragma unroll
    for (int i = 0; i < 4; i++) {
        m_i[i] = -3.0e38f; l_i[i] = 0.f;
        #pragma unroll
        for (int j = 0; j < 4; j++) acc[i][j] = 0.f;
    }
    const float scale = 0.125f;  // 1/sqrt(64)

    for (int kt = 0; kt < MK; kt += 64) {
        __syncthreads();  // prev-iter KVs/Ps reads done; Qs visible (first iter)
        // Load K tile [64 k][64 d]
        for (int t = tid; t < 64 * 64; t += 256) {
            int r = t >> 6, c = t & 63;
            KVs[r][c] = Kbase[(size_t)(kt + r) * INNER + c];
        }
        if (tid < 64) msk[tid] = (mb[kt + tid] != 0) ? 0.f : -1.0e30f;
        __syncthreads();

        // S = Q K^T (owned 4x4)
        float s[4][4];
        #pragma unroll
        for (int i = 0; i < 4; i++)
            #pragma unroll
            for (int j = 0; j < 4; j++) s[i][j] = 0.f;
        #pragma unroll 8
        for (int d = 0; d < 64; d++) {
            float a[4], kr[4];
            #pragma unroll
            for (int i = 0; i < 4; i++) a[i] = Qs[ty * 4 + i][d];
            #pragma unroll
            for (int j = 0; j < 4; j++) kr[j] = KVs[tx * 4 + j][d];
            #pragma unroll
            for (int i = 0; i < 4; i++)
                #pragma unroll
                for (int j = 0; j < 4; j++) s[i][j] = fmaf(a[i], kr[j], s[i][j]);
        }

        // scale + mask + online softmax update
        #pragma unroll
        for (int i = 0; i < 4; i++) {
            float mx = -3.0e38f;
            #pragma unroll
            for (int j = 0; j < 4; j++) {
                s[i][j] = s[i][j] * scale + msk[tx * 4 + j];
                mx = fmaxf(mx, s[i][j]);
            }
            #pragma unroll
            for (int off = 8; off; off >>= 1)
                mx = fmaxf(mx, __shfl_xor_sync(0xffffffffu, mx, off));

            float mnew = fmaxf(m_i[i], mx);
            float corr = __expf(m_i[i] - mnew);
            float lsum = 0.f;
            #pragma unroll
            for (int j = 0; j < 4; j++) {
                float p = __expf(s[i][j] - mnew);
                s[i][j] = p;
                lsum += p;
            }
            #pragma unroll
            for (int off = 8; off; off >>= 1)
                lsum += __shfl_xor_sync(0xffffffffu, lsum, off);

            l_i[i] = l_i[i] * corr + lsum;
            m_i[i] = mnew;
            #pragma unroll
            for (int j = 0; j < 4; j++) acc[i][j] *= corr;
            #pragma unroll
            for (int j = 0; j < 4; j++) Ps[ty * 4 + i][tx * 4 + j] = s[i][j];
        }
        __syncthreads();  // P written; K-tile reads done -> reuse KVs for V

        for (int t = tid; t < 64 * 64; t += 256) {
            int r = t >> 6, c = t & 63;
            KVs[r][c] = Vbase[(size_t)(kt + r) * INNER + c];
        }
        __syncthreads();

        // acc += P @ V (owned rows = same query rows, cols = dim cols)
        #pragma unroll 8
        for (int k = 0; k < 64; k++) {
            float p[4], v[4];
            #pragma unroll
            for (int i = 0; i < 4; i++) p[i] = Ps[ty * 4 + i][k];
            #pragma unroll
            for (int j = 0; j < 4; j++) v[j] = KVs[k][tx * 4 + j];
            #pragma unroll
            for (int i = 0; i < 4; i++)
                #pragma unroll
                for (int j = 0; j < 4; j++) acc[i][j] = fmaf(p[i], v[j], acc[i][j]);
        }
    }

    // Write O
    #pragma unroll
    for (int i = 0; i < 4; i++) {
        const float inv = 1.f / l_i[i];
        const int q = q0 + ty * 4 + i;
        float4 v = make_float4(acc[i][0] * inv, acc[i][1] * inv,
                               acc[i][2] * inv, acc[i][3] * inv);
        *(float4*)(O + (size_t)(b * NQ + q) * INNER + h * DHEAD + tx * 4) = v;
    }
}

// ----------------------------------------------------------------------------
// kernel_launch
// Inputs: 0=x [B,N,DIM] f32, 1=context [B,M,CTXD] f32, 2=mask [B,M] (bool
// promoted to int32 by the harness), 3=Wq [DIM,INNER], 4=Wk [CTXD,INNER],
// 5=Wv [CTXD,INNER], 6=Wo [INNER,DIM], 7=bo [DIM]
// Output: [B,N,DIM] f32
// ----------------------------------------------------------------------------
extern "C" void kernel_launch(void* const* d_in, const int* in_sizes, int n_in,
                              void* d_out, int out_size)
{
    const float* x    = (const float*)d_in[0];
    const float* ctx  = (const float*)d_in[1];
    const int*   mask = (const int*)d_in[2];
    const float* Wq   = (const float*)d_in[3];
    const float* Wk   = (const float*)d_in[4];
    const float* Wv   = (const float*)d_in[5];
    const float* Wo   = (const float*)d_in[6];
    const float* bo   = (const float*)d_in[7];
    float* out = (float*)d_out;

    float *pQ, *pK, *pV, *pO;
    cudaGetSymbolAddress((void**)&pQ, g_Q);
    cudaGetSymbolAddress((void**)&pK, g_K);
    cudaGetSymbolAddress((void**)&pV, g_V);
    cudaGetSymbolAddress((void**)&pO, g_O);

    const int rowsX = BSZ * NQ;   // 8192
    const int rowsC = BSZ * MK;   // 8192

    // Q = x @ Wq          [8192,1024]@[1024,512]
    {
        dim3 grid(INNER / 64, rowsX / 128);
        sgemm_kernel<<<grid, 256>>>(x, Wq, pQ, nullptr, rowsX, INNER, DIMX);
    }
    // K = ctx @ Wk, V = ctx @ Wv
    {
        dim3 grid(INNER / 64, rowsC / 128);
        sgemm_kernel<<<grid, 256>>>(ctx, Wk, pK, nullptr, rowsC, INNER, CTXD);
        sgemm_kernel<<<grid, 256>>>(ctx, Wv, pV, nullptr, rowsC, INNER, CTXD);
    }
    // Flash attention
    {
        cudaFuncSetAttribute(flash_kernel,
                             cudaFuncAttributeMaxDynamicSharedMemorySize,
                             FLASH_SMEM_FLOATS * (int)sizeof(float));
        dim3 grid(NQ / 64, BSZ * HEADS);
        flash_kernel<<<grid, 256, FLASH_SMEM_FLOATS * sizeof(float)>>>(
            pQ, pK, pV, mask, pO);
    }
    // out = O @ Wo + bo   [8192,512]@[512,1024]
    {
        dim3 grid(DIMX / 64, rowsX / 128);
        sgemm_kernel<<<grid, 256>>>(pO, Wo, out, bo, rowsX, DIMX, INNER);
    }
}

// round 3
// speedup vs baseline: 1.3184x; 1.3184x over previous
#include <cuda_runtime.h>
#include <math.h>
#include <stdint.h>

// Problem constants
#define BSZ   4
#define NQ    2048
#define MK    2048
#define DIMX  1024
#define CTXD  1024
#define HEADS 8
#define DHEAD 64
#define INNER 512   // HEADS * DHEAD

// Scratch (allocation-free rule: __device__ globals)
__device__ float g_Q[(size_t)BSZ * NQ * INNER];
__device__ float g_K[(size_t)BSZ * MK * INNER];
__device__ float g_V[(size_t)BSZ * MK * INNER];
__device__ float g_O[(size_t)BSZ * NQ * INNER];

// ----------------------------------------------------------------------------
// 3xTF32 helpers: hi = tf32(x), lo = tf32(x - hi). hi*bh + hi*bl + lo*bh gives
// ~fp32 accuracy (the lo*lo term is ~2^-22 relative, negligible).
// ----------------------------------------------------------------------------
__device__ __forceinline__ uint32_t f2tf(float x) {
    uint32_t u;
    asm("cvt.rna.tf32.f32 %0, %1;" : "=r"(u) : "f"(x));
    return u;
}
__device__ __forceinline__ void split_tf32(float x, uint32_t& h, uint32_t& l) {
    h = f2tf(x);
    l = f2tf(x - __uint_as_float(h));
}
__device__ __forceinline__ void mma8(float c[4], const uint32_t a[4], const uint32_t b[2]) {
    asm volatile(
        "mma.sync.aligned.m16n8k8.row.col.f32.tf32.tf32.f32 "
        "{%0,%1,%2,%3},{%4,%5,%6,%7},{%8,%9},{%0,%1,%2,%3};"
        : "+f"(c[0]), "+f"(c[1]), "+f"(c[2]), "+f"(c[3])
        : "r"(a[0]), "r"(a[1]), "r"(a[2]), "r"(a[3]), "r"(b[0]), "r"(b[1]));
}
__device__ __forceinline__ void mma_x3(float c[4],
                                       const uint32_t ah[4], const uint32_t al[4],
                                       const uint32_t bh[2], const uint32_t bl[2]) {
    mma8(c, ah, bh);
    mma8(c, ah, bl);
    mma8(c, al, bh);
}

// ----------------------------------------------------------------------------
// Tensor-core GEMM: C[M,N] = A[M,K] @ W[K,N] (+bias), 3xTF32.
// BM=128, BN=64, BK=16. 256 threads = 8 warps in a 4(m)x2(n) grid;
// warp tile 32x32 = 2 m16 x 4 n8 fragments.
// Smem padded so fragment loads are bank-conflict-free (stride%32==4).
// ----------------------------------------------------------------------------
#define ASTR 132
#define BSTR 68

__global__ __launch_bounds__(256)
void gemm_tc(const float* __restrict__ A, const float* __restrict__ W,
             float* __restrict__ C, const float* __restrict__ bias,
             int M, int N, int K)
{
    __shared__ float Ast[16][ASTR];   // [k][m]
    __shared__ float Bs[16][BSTR];    // [k][n]

    const int tid = threadIdx.x;
    const int lane = tid & 31, warp = tid >> 5;
    const int wm = warp & 3, wn = warp >> 2;
    const int g = lane >> 2, t = lane & 3;
    const int m0 = blockIdx.y * 128, n0 = blockIdx.x * 64;

    // staging maps
    const int lm = tid >> 1, lk = (tid & 1) * 8;
    const int bkr = tid >> 4, bn = (tid & 15) * 4;

    float acc[2][4][4];
    #pragma unroll
    for (int mt = 0; mt < 2; mt++)
        #pragma unroll
        for (int nt = 0; nt < 4; nt++)
            #pragma unroll
            for (int i = 0; i < 4; i++) acc[mt][nt][i] = 0.f;

    for (int k0 = 0; k0 < K; k0 += 16) {
        const float* ap = A + (size_t)(m0 + lm) * K + k0 + lk;
        float4 a0 = *(const float4*)ap;
        float4 a1 = *(const float4*)(ap + 4);
        Ast[lk + 0][lm] = a0.x; Ast[lk + 1][lm] = a0.y;
        Ast[lk + 2][lm] = a0.z; Ast[lk + 3][lm] = a0.w;
        Ast[lk + 4][lm] = a1.x; Ast[lk + 5][lm] = a1.y;
        Ast[lk + 6][lm] = a1.z; Ast[lk + 7][lm] = a1.w;
        *(float4*)&Bs[bkr][bn] = *(const float4*)(W + (size_t)(k0 + bkr) * N + n0 + bn);
        __syncthreads();

        #pragma unroll
        for (int s = 0; s < 16; s += 8) {
            uint32_t ah[2][4], al[2][4];
            #pragma unroll
            for (int mt = 0; mt < 2; mt++) {
                const int mr = wm * 32 + mt * 16;
                split_tf32(Ast[s + t    ][mr + g    ], ah[mt][0], al[mt][0]);
                split_tf32(Ast[s + t    ][mr + g + 8], ah[mt][1], al[mt][1]);
                split_tf32(Ast[s + t + 4][mr + g    ], ah[mt][2], al[mt][2]);
                split_tf32(Ast[s + t + 4][mr + g + 8], ah[mt][3], al[mt][3]);
            }
            #pragma unroll
            for (int nt = 0; nt < 4; nt++) {
                const int nc = wn * 32 + nt * 8 + g;
                uint32_t bh[2], bl[2];
                split_tf32(Bs[s + t    ][nc], bh[0], bl[0]);
                split_tf32(Bs[s + t + 4][nc], bh[1], bl[1]);
                mma_x3(acc[0][nt], ah[0], al[0], bh, bl);
                mma_x3(acc[1][nt], ah[1], al[1], bh, bl);
            }
        }
        __syncthreads();
    }

    // writeback (c0,c1 -> row g; c2,c3 -> row g+8; cols 2t,2t+1)
    #pragma unroll
    for (int mt = 0; mt < 2; mt++) {
        const int r0 = m0 + wm * 32 + mt * 16 + g;
        #pragma unroll
        for (int nt = 0; nt < 4; nt++) {
            const int c0 = n0 + wn * 32 + nt * 8 + t * 2;
            float2 v0 = make_float2(acc[mt][nt][0], acc[mt][nt][1]);
            float2 v1 = make_float2(acc[mt][nt][2], acc[mt][nt][3]);
            if (bias) {
                float b0v = bias[c0], b1v = bias[c0 + 1];
                v0.x += b0v; v0.y += b1v;
                v1.x += b0v; v1.y += b1v;
            }
            *(float2*)(C + (size_t)r0 * N + c0) = v0;
            *(float2*)(C + (size_t)(r0 + 8) * N + c0) = v1;
        }
    }
}

// ----------------------------------------------------------------------------
// Tensor-core flash attention, 3xTF32. Per CTA: 64 queries, one (b,h).
// 128 threads = 4 warps, warp owns 16 q-rows x all 64 keys (8 n8 tiles).
// Online softmax on fragment rows (quad shuffles). P round-trips via smem
// to convert C-fragment layout -> A-fragment layout.
// ----------------------------------------------------------------------------
#define FSTR 68
#define FLASH_SMEM_BYTES ((3 * 64 * FSTR + 64) * (int)sizeof(float))

__global__ __launch_bounds__(128)
void flash_tc(const float* __restrict__ Q, const float* __restrict__ K,
              const float* __restrict__ V, const int* __restrict__ mask,
              float* __restrict__ O)
{
    extern __shared__ float sm[];
    float (*Qs)[FSTR]  = (float (*)[FSTR])sm;                  // [q][d]
    float (*KVs)[FSTR] = (float (*)[FSTR])(sm + 64 * FSTR);    // [k][d]
    float (*Ps)[FSTR]  = (float (*)[FSTR])(sm + 2 * 64 * FSTR);// [q][k]
    float* msk = sm + 3 * 64 * FSTR;

    const int bh = blockIdx.y;
    const int b = bh >> 3, h = bh & 7;
    const int q0 = blockIdx.x * 64;

    const int tid = threadIdx.x;
    const int lane = tid & 31, warp = tid >> 5;
    const int g = lane >> 2, t = lane & 3;
    const int pr = warp * 16;   // warp's local q-row base

    const float* Qb = Q + (size_t)b * NQ * INNER + (size_t)h * DHEAD;
    const float* Kb = K + (size_t)b * MK * INNER + (size_t)h * DHEAD;
    const float* Vb = V + (size_t)b * MK * INNER + (size_t)h * DHEAD;
    const int* mb = mask + (size_t)b * MK;

    // stage Q tile [64 q][64 d]
    for (int i = tid; i < 64 * 16; i += 128) {
        int r = i >> 4, c = (i & 15) * 4;
        *(float4*)&Qs[r][c] = *(const float4*)(Qb + (size_t)(q0 + r) * INNER + c);
    }

    float of[8][4];
    #pragma unroll
    for (int nt = 0; nt < 8; nt++)
        #pragma unroll
        for (int i = 0; i < 4; i++) of[nt][i] = 0.f;
    float mrow0 = -3.0e38f, mrow1 = -3.0e38f, lrow0 = 0.f, lrow1 = 0.f;
    const float scale = 0.125f;

    for (int kt = 0; kt < MK; kt += 64) {
        __syncthreads();   // prev PV reads of KVs done; Qs staged (first iter)
        for (int i = tid; i < 64 * 16; i += 128) {
            int r = i >> 4, c = (i & 15) * 4;
            *(float4*)&KVs[r][c] = *(const float4*)(Kb + (size_t)(kt + r) * INNER + c);
        }
        if (tid < 64) msk[tid] = (mb[kt + tid] != 0) ? 0.f : -1.0e30f;
        __syncthreads();

        // ---- S = Q K^T over this 64-key tile ----
        float sf[8][4];
        #pragma unroll
        for (int nt = 0; nt < 8; nt++)
            #pragma unroll
            for (int i = 0; i < 4; i++) sf[nt][i] = 0.f;

        #pragma unroll
        for (int s = 0; s < 64; s += 8) {
            uint32_t ah[4], al[4];
            split_tf32(Qs[pr + g    ][s + t    ], ah[0], al[0]);
            split_tf32(Qs[pr + g + 8][s + t    ], ah[1], al[1]);
            split_tf32(Qs[pr + g    ][s + t + 4], ah[2], al[2]);
            split_tf32(Qs[pr + g + 8][s + t + 4], ah[3], al[3]);
            #pragma unroll
            for (int nt = 0; nt < 8; nt++) {
                uint32_t bh2[2], bl2[2];
                split_tf32(KVs[nt * 8 + g][s + t    ], bh2[0], bl2[0]);
                split_tf32(KVs[nt * 8 + g][s + t + 4], bh2[1], bl2[1]);
                mma_x3(sf[nt], ah, al, bh2, bl2);
            }
        }

        // ---- scale + mask + online softmax (rows g and g+8 of this warp) ----
        float mx0 = -3.0e38f, mx1 = -3.0e38f;
        #pragma unroll
        for (int nt = 0; nt < 8; nt++) {
            float mk0 = msk[nt * 8 + 2 * t], mk1 = msk[nt * 8 + 2 * t + 1];
            sf[nt][0] = sf[nt][0] * scale + mk0;
            sf[nt][1] = sf[nt][1] * scale + mk1;
            sf[nt][2] = sf[nt][2] * scale + mk0;
            sf[nt][3] = sf[nt][3] * scale + mk1;
            mx0 = fmaxf(mx0, fmaxf(sf[nt][0], sf[nt][1]));
            mx1 = fmaxf(mx1, fmaxf(sf[nt][2], sf[nt][3]));
        }
        mx0 = fmaxf(mx0, __shfl_xor_sync(0xffffffffu, mx0, 1));
        mx0 = fmaxf(mx0, __shfl_xor_sync(0xffffffffu, mx0, 2));
        mx1 = fmaxf(mx1, __shfl_xor_sync(0xffffffffu, mx1, 1));
        mx1 = fmaxf(mx1, __shfl_xor_sync(0xffffffffu, mx1, 2));

        const float mn0 = fmaxf(mrow0, mx0), mn1 = fmaxf(mrow1, mx1);
        const float corr0 = __expf(mrow0 - mn0), corr1 = __expf(mrow1 - mn1);
        float ls0 = 0.f, ls1 = 0.f;
        #pragma unroll
        for (int nt = 0; nt < 8; nt++) {
            sf[nt][0] = __expf(sf[nt][0] - mn0);
            sf[nt][1] = __expf(sf[nt][1] - mn0);
            sf[nt][2] = __expf(sf[nt][2] - mn1);
            sf[nt][3] = __expf(sf[nt][3] - mn1);
            ls0 += sf[nt][0] + sf[nt][1];
            ls1 += sf[nt][2] + sf[nt][3];
        }
        ls0 += __shfl_xor_sync(0xffffffffu, ls0, 1);
        ls0 += __shfl_xor_sync(0xffffffffu, ls0, 2);
        ls1 += __shfl_xor_sync(0xffffffffu, ls1, 1);
        ls1 += __shfl_xor_sync(0xffffffffu, ls1, 2);

        lrow0 = lrow0 * corr0 + ls0; mrow0 = mn0;
        lrow1 = lrow1 * corr1 + ls1; mrow1 = mn1;

        #pragma unroll
        for (int nt = 0; nt < 8; nt++) {
            of[nt][0] *= corr0; of[nt][1] *= corr0;
            of[nt][2] *= corr1; of[nt][3] *= corr1;
        }

        // write P to smem (own rows only)
        #pragma unroll
        for (int nt = 0; nt < 8; nt++) {
            Ps[pr + g    ][nt * 8 + 2 * t    ] = sf[nt][0];
            Ps[pr + g    ][nt * 8 + 2 * t + 1] = sf[nt][1];
            Ps[pr + g + 8][nt * 8 + 2 * t    ] = sf[nt][2];
            Ps[pr + g + 8][nt * 8 + 2 * t + 1] = sf[nt][3];
        }

        __syncthreads();   // all warps done reading K from KVs
        for (int i = tid; i < 64 * 16; i += 128) {
            int r = i >> 4, c = (i & 15) * 4;
            *(float4*)&KVs[r][c] = *(const float4*)(Vb + (size_t)(kt + r) * INNER + c);
        }
        __syncthreads();   // V staged + own Ps visible

        // ---- O += P @ V ----
        #pragma unroll
        for (int s = 0; s < 64; s += 8) {   // keys
            uint32_t ah[4], al[4];
            split_tf32(Ps[pr + g    ][s + t    ], ah[0], al[0]);
            split_tf32(Ps[pr + g + 8][s + t    ], ah[1], al[1]);
            split_tf32(Ps[pr + g    ][s + t + 4], ah[2], al[2]);
            split_tf32(Ps[pr + g + 8][s + t + 4], ah[3], al[3]);
            #pragma unroll
            for (int nt = 0; nt < 8; nt++) {
                uint32_t bh2[2], bl2[2];
                split_tf32(KVs[s + t    ][nt * 8 + g], bh2[0], bl2[0]);
                split_tf32(KVs[s + t + 4][nt * 8 + g], bh2[1], bl2[1]);
                mma_x3(of[nt], ah, al, bh2, bl2);
            }
        }
    }

    // epilogue: divide by l, write O [B,N,INNER]
    const float inv0 = 1.f / lrow0, inv1 = 1.f / lrow1;
    const int qa = q0 + pr + g;
    #pragma unroll
    for (int nt = 0; nt < 8; nt++) {
        const int col = h * DHEAD + nt * 8 + 2 * t;
        float2 v0 = make_float2(of[nt][0] * inv0, of[nt][1] * inv0);
        float2 v1 = make_float2(of[nt][2] * inv1, of[nt][3] * inv1);
        *(float2*)(O + (size_t)(b * NQ + qa) * INNER + col) = v0;
        *(float2*)(O + (size_t)(b * NQ + qa + 8) * INNER + col) = v1;
    }
}

// ----------------------------------------------------------------------------
// kernel_launch
// Inputs: 0=x, 1=context, 2=mask (int32), 3=Wq, 4=Wk, 5=Wv, 6=Wo, 7=bo
// ----------------------------------------------------------------------------
extern "C" void kernel_launch(void* const* d_in, const int* in_sizes, int n_in,
                              void* d_out, int out_size)
{
    const float* x    = (const float*)d_in[0];
    const float* ctx  = (const float*)d_in[1];
    const int*   mask = (const int*)d_in[2];
    const float* Wq   = (const float*)d_in[3];
    const float* Wk   = (const float*)d_in[4];
    const float* Wv   = (const float*)d_in[5];
    const float* Wo   = (const float*)d_in[6];
    const float* bo   = (const float*)d_in[7];
    float* out = (float*)d_out;

    float *pQ, *pK, *pV, *pO;
    cudaGetSymbolAddress((void**)&pQ, g_Q);
    cudaGetSymbolAddress((void**)&pK, g_K);
    cudaGetSymbolAddress((void**)&pV, g_V);
    cudaGetSymbolAddress((void**)&pO, g_O);

    const int rowsX = BSZ * NQ;   // 8192
    const int rowsC = BSZ * MK;   // 8192

    {   // projections
        dim3 gq(INNER / 64, rowsX / 128);
        gemm_tc<<<gq, 256>>>(x, Wq, pQ, nullptr, rowsX, INNER, DIMX);
        dim3 gk(INNER / 64, rowsC / 128);
        gemm_tc<<<gk, 256>>>(ctx, Wk, pK, nullptr, rowsC, INNER, CTXD);
        gemm_tc<<<gk, 256>>>(ctx, Wv, pV, nullptr, rowsC, INNER, CTXD);
    }
    {   // flash attention
        cudaFuncSetAttribute(flash_tc,
                             cudaFuncAttributeMaxDynamicSharedMemorySize,
                             FLASH_SMEM_BYTES);
        dim3 grid(NQ / 64, BSZ * HEADS);
        flash_tc<<<grid, 128, FLASH_SMEM_BYTES>>>(pQ, pK, pV, mask, pO);
    }
    {   // out = O @ Wo + bo
        dim3 go(DIMX / 64, rowsX / 128);
        gemm_tc<<<go, 256>>>(pO, Wo, out, bo, rowsX, DIMX, INNER);
    }
}